// round 12
// baseline (speedup 1.0000x reference)
#include <cuda_runtime.h>
#include <cuda_bf16.h>
#include <cstdint>

// Problem constants (fixed by setup_inputs): B=2, L=2048, E=512, window=64
#define L_SEQ   2048
#define E_DIM   512
#define B_BATCH 2
#define M_ROWS  (B_BATCH * L_SEQ)   // 4096

// ---------------- scratch (device globals; no allocation allowed) ----------
__device__ float g_q[M_ROWS * E_DIM];
__device__ float g_k[M_ROWS * E_DIM];
__device__ float g_v[M_ROWS * E_DIM];

typedef unsigned long long u64;

__device__ __forceinline__ u64 pk2(float lo, float hi) {
    u64 r;
    asm("mov.b64 %0, {%1,%2};" : "=l"(r) : "f"(lo), "f"(hi));
    return r;
}
__device__ __forceinline__ void fma2(u64 &d, u64 a, u64 b) {
    asm("fma.rn.f32x2 %0, %1, %2, %0;" : "+l"(d) : "l"(a), "l"(b));
}
__device__ __forceinline__ void unpk2(float &lo, float &hi, u64 v) {
    asm("mov.b64 {%0,%1}, %2;" : "=f"(lo), "=f"(hi) : "l"(v));
}

// ============================================================================
// Kernel 1: QKV projection on TENSOR CORES (tf32 mma.sync.m16n8k8).
//   out[m][f] = sum_e X[m][e] * W[f][e] + b[f]
// BM=128, BN=64, BK=16, 256 threads (8 warps, 4x2 warp grid, 32x32 warp tile).
// Operands held in smem as tf32 bits, m-major/n-major with row stride 20:
//   fragment-load bank = (20*lr + kq) % 32 -> all 32 banks distinct
//   => ZERO conflicts in the hot loop (16 LDS.32 + 8 HMMA per k-step of 8).
// fp32 -> tf32 via cvt.rna at smem-fill time (once per element).
// Double-buffered tiles, register-staged prefetch, 1 syncthreads per tile.
// ============================================================================
#define BM 128
#define BN 64
#define BK 16
#define KSTR (BK + 4)   // 20 -> conflict-free fragment loads

__device__ __forceinline__ uint32_t cvt_tf32(float f) {
    uint32_t u;
    asm("cvt.rna.tf32.f32 %0, %1;" : "=r"(u) : "f"(f));
    return u;
}

__device__ __forceinline__ void mma_tf32(float c[4], const uint32_t a[4], const uint32_t b[2]) {
    asm volatile(
        "mma.sync.aligned.m16n8k8.row.col.f32.tf32.tf32.f32 "
        "{%0,%1,%2,%3}, {%4,%5,%6,%7}, {%8,%9}, {%0,%1,%2,%3};"
        : "+f"(c[0]), "+f"(c[1]), "+f"(c[2]), "+f"(c[3])
        : "r"(a[0]), "r"(a[1]), "r"(a[2]), "r"(a[3]), "r"(b[0]), "r"(b[1]));
}

__global__ void __launch_bounds__(256, 2) qkv_gemm(
    const float* __restrict__ X,
    const float* __restrict__ Wq, const float* __restrict__ Wk, const float* __restrict__ Wv,
    const float* __restrict__ bq, const float* __restrict__ bk, const float* __restrict__ bv)
{
    __shared__ uint32_t As[2][BM][KSTR];   // 20480 B
    __shared__ uint32_t Bs[2][BN][KSTR];   // 10240 B

    const int t    = threadIdx.x;
    const int warp = t >> 5, lane = t & 31;
    const int wm   = warp & 3;             // 4 warps along M (32 rows each)
    const int wn   = warp >> 2;            // 2 warps along N (32 cols each)
    const int kq   = lane & 3;             // thread-in-group (k / col-pair idx)
    const int lr   = lane >> 2;            // group id (row idx)

    const int m0  = blockIdx.x * BM;
    const int nb  = blockIdx.y;            // 0..23
    const int mat = nb >> 3;               // 0=q, 1=k, 2=v
    const int f0  = (nb & 7) * BN;

    const float* W    = (mat == 0) ? Wq : (mat == 1) ? Wk : Wv;
    const float* bias = (mat == 0) ? bq : (mat == 1) ? bk : bv;
    float*       out  = (mat == 0) ? g_q : (mat == 1) ? g_k : g_v;

    // loader mapping
    const int ra = t >> 1;                 // 0..127  A row (m)
    const int ca = (t & 1) * 8;            // 0 or 8  A k-col base (8 cols)
    const int rb = t >> 2;                 // 0..63   B row (n)
    const int cb = (t & 3) * 4;            // 0..12   B k-col base (4 cols)

    const float* Ag = X + (size_t)(m0 + ra) * E_DIM + ca;
    const float* Bg = W + (size_t)(f0 + rb) * E_DIM + cb;

    // prologue: tile 0
    {
        float4 a0 = *(const float4*)(Ag);
        float4 a1 = *(const float4*)(Ag + 4);
        float4 b0 = *(const float4*)(Bg);
        uint4 ua0 = make_uint4(cvt_tf32(a0.x), cvt_tf32(a0.y), cvt_tf32(a0.z), cvt_tf32(a0.w));
        uint4 ua1 = make_uint4(cvt_tf32(a1.x), cvt_tf32(a1.y), cvt_tf32(a1.z), cvt_tf32(a1.w));
        uint4 ub0 = make_uint4(cvt_tf32(b0.x), cvt_tf32(b0.y), cvt_tf32(b0.z), cvt_tf32(b0.w));
        *(uint4*)&As[0][ra][ca]     = ua0;
        *(uint4*)&As[0][ra][ca + 4] = ua1;
        *(uint4*)&Bs[0][rb][cb]     = ub0;
    }
    __syncthreads();

    float acc[2][4][4];
#pragma unroll
    for (int mt = 0; mt < 2; mt++)
#pragma unroll
        for (int nt = 0; nt < 4; nt++)
#pragma unroll
            for (int i = 0; i < 4; i++) acc[mt][nt][i] = 0.f;

    int buf = 0;
    for (int kt = 0; kt < E_DIM; kt += BK) {
        float4 na0, na1, nb0;
        const bool more = (kt + BK) < E_DIM;
        if (more) {
            na0 = *(const float4*)(Ag + kt + BK);
            na1 = *(const float4*)(Ag + kt + BK + 4);
            nb0 = *(const float4*)(Bg + kt + BK);
        }

#pragma unroll
        for (int ks = 0; ks < BK; ks += 8) {
            uint32_t af[2][4], bf[4][2];
#pragma unroll
            for (int mt = 0; mt < 2; mt++) {
                int m = wm * 32 + mt * 16 + lr;
                af[mt][0] = As[buf][m][ks + kq];        // a0: (row, k)
                af[mt][1] = As[buf][m + 8][ks + kq];    // a1: (row+8, k)
                af[mt][2] = As[buf][m][ks + kq + 4];    // a2: (row, k+4)
                af[mt][3] = As[buf][m + 8][ks + kq + 4];// a3: (row+8, k+4)
            }
#pragma unroll
            for (int nt = 0; nt < 4; nt++) {
                int n = wn * 32 + nt * 8 + lr;
                bf[nt][0] = Bs[buf][n][ks + kq];        // b0: (k, col)
                bf[nt][1] = Bs[buf][n][ks + kq + 4];    // b1: (k+4, col)
            }
#pragma unroll
            for (int mt = 0; mt < 2; mt++)
#pragma unroll
                for (int nt = 0; nt < 4; nt++)
                    mma_tf32(acc[mt][nt], af[mt], bf[nt]);
        }

        if (more) {
            int nbuf = buf ^ 1;
            uint4 ua0 = make_uint4(cvt_tf32(na0.x), cvt_tf32(na0.y), cvt_tf32(na0.z), cvt_tf32(na0.w));
            uint4 ua1 = make_uint4(cvt_tf32(na1.x), cvt_tf32(na1.y), cvt_tf32(na1.z), cvt_tf32(na1.w));
            uint4 ub0 = make_uint4(cvt_tf32(nb0.x), cvt_tf32(nb0.y), cvt_tf32(nb0.z), cvt_tf32(nb0.w));
            *(uint4*)&As[nbuf][ra][ca]     = ua0;
            *(uint4*)&As[nbuf][ra][ca + 4] = ua1;
            *(uint4*)&Bs[nbuf][rb][cb]     = ub0;
        }
        __syncthreads();
        buf ^= 1;
    }

    // epilogue: bias + store (c0,c1 = cols 2kq,2kq+1 @ row; c2,c3 @ row+8)
#pragma unroll
    for (int mt = 0; mt < 2; mt++) {
#pragma unroll
        for (int nt = 0; nt < 4; nt++) {
            int row = m0 + wm * 32 + mt * 16 + lr;
            int col = f0 + wn * 32 + nt * 8 + 2 * kq;
            float2 bb = *(const float2*)(bias + col);
            *(float2*)(out + (size_t)row * E_DIM + col) =
                make_float2(acc[mt][nt][0] + bb.x, acc[mt][nt][1] + bb.y);
            *(float2*)(out + (size_t)(row + 8) * E_DIM + col) =
                make_float2(acc[mt][nt][2] + bb.x, acc[mt][nt][3] + bb.y);
        }
    }
}

// ============================================================================
// Kernel 2: sliding-window attention (UNCHANGED from R9 for clean attribution).
// ============================================================================
#define QB  16
#define KBW 144           // QB + 2*64
#define ECA 32            // e-chunk, score phase
#define ECB 64            // e-chunk, PV phase

__global__ void __launch_bounds__(256) local_attn(float* __restrict__ out)
{
    __shared__ float sKV[KBW][ECB];       // 36864 B (phase A uses cols 0..31)
    __shared__ float sQt[8][QB][4];       //  2048 B (transposed Q chunk)
    __shared__ float P[KBW][QB + 1];      //  9792 B (k-major probs)

    const int t    = threadIdx.x;
    const int blk  = blockIdx.x;
    const int b    = blk >> 7;            // 128 query-blocks per batch
    const int l0   = (blk & 127) * QB;
    const int rowbase = b * L_SEQ + l0;
    const int kbase   = l0 - 64;          // global index of local key 0

    const int qi = t & 15;                // this thread's query
    const int kg = t >> 4;                // key sub-lane 0..15

    u64 acc2[9];
#pragma unroll
    for (int i = 0; i < 9; i++) acc2[i] = 0ull;

    // ---------------- Phase A: scores S[q][j] = q . k_j ----------------
    for (int ec = 0; ec < E_DIM; ec += ECA) {
        if (t < 128) {                    // load sQt: 16 q x 8 e4-chunks
            int r = t >> 3, c = t & 7;
            *(float4*)&sQt[c][r][0] =
                *(const float4*)(g_q + (size_t)(rowbase + r) * E_DIM + ec + c * 4);
        }
        for (int idx = t; idx < KBW * (ECA / 4); idx += 256) {  // sK 144x32
            int r = idx >> 3;
            int c4 = (idx & 7) * 4;
            int g = kbase + r;
            float4 v = (g >= 0 && g < L_SEQ)
                ? *(const float4*)(g_k + (size_t)(b * L_SEQ + g) * E_DIM + ec + c4)
                : make_float4(0.f, 0.f, 0.f, 0.f);
            *(float4*)&sKV[r][c4] = v;
        }
        __syncthreads();

#pragma unroll
        for (int e4 = 0; e4 < 8; e4++) {
            ulonglong2 qp = *(const ulonglong2*)&sQt[e4][qi][0];  // conflict-free
#pragma unroll
            for (int i = 0; i < 9; i++) {
                ulonglong2 kp = *(const ulonglong2*)&sKV[kg + 16 * i][e4 * 4];
                fma2(acc2[i], qp.x, kp.x);
                fma2(acc2[i], qp.y, kp.y);
            }
        }
        __syncthreads();
    }

    // scale + mask -> P (k-major)
    const float scale = 0.044194173824159216f;   // 1/sqrt(512)
#pragma unroll
    for (int i = 0; i < 9; i++) {
        int j = kg + 16 * i;
        int g = kbase + j;
        float lo, hi;
        unpk2(lo, hi, acc2[i]);
        float s = lo + hi;
        bool valid = (g >= 0) && (g < L_SEQ) && (j >= qi) && (j <= qi + 128);
        P[j][qi] = valid ? s * scale : -3.0e38f;
    }
    __syncthreads();

    // ---------------- softmax: 8 warps x 2 queries ----------------
    {
        const int warp = t >> 5, lane = t & 31;
#pragma unroll
        for (int qq = 0; qq < 2; qq++) {
            int q = warp * 2 + qq;
            float v[5];
#pragma unroll
            for (int i = 0; i < 5; i++) {
                int k = lane + 32 * i;
                v[i] = (k < KBW) ? P[k][q] : -3.0e38f;
            }
            float mx = v[0];
#pragma unroll
            for (int i = 1; i < 5; i++) mx = fmaxf(mx, v[i]);
#pragma unroll
            for (int o = 16; o; o >>= 1) mx = fmaxf(mx, __shfl_xor_sync(0xffffffffu, mx, o));
            float s = 0.f;
#pragma unroll
            for (int i = 0; i < 5; i++) { v[i] = __expf(v[i] - mx); s += v[i]; }
#pragma unroll
            for (int o = 16; o; o >>= 1) s += __shfl_xor_sync(0xffffffffu, s, o);
            float inv = 1.0f / s;
#pragma unroll
            for (int i = 0; i < 5; i++) {
                int k = lane + 32 * i;
                if (k < KBW) P[k][q] = v[i] * inv;
            }
        }
    }
    __syncthreads();

    // ---------------- Phase B: out[q][e] = sum_j P[j][q] * v_j[e] ----------
    const int e4 = (t >> 4) * 4;          // 0..60
    for (int ec = 0; ec < E_DIM; ec += ECB) {
        for (int idx = t; idx < KBW * (ECB / 4); idx += 256) {  // sV 144x64
            int r = idx >> 4;
            int c4 = (idx & 15) * 4;
            int g = kbase + r;
            float4 v = (g >= 0 && g < L_SEQ)
                ? *(const float4*)(g_v + (size_t)(b * L_SEQ + g) * E_DIM + ec + c4)
                : make_float4(0.f, 0.f, 0.f, 0.f);
            *(float4*)&sKV[r][c4] = v;
        }
        __syncthreads();

        float4 o = make_float4(0.f, 0.f, 0.f, 0.f);
#pragma unroll 8
        for (int j = 0; j < KBW; j++) {
            float p = P[j][qi];                          // conflict-free (stride 17)
            float4 vv = *(const float4*)&sKV[j][e4];     // 2-addr broadcast
            o.x += p * vv.x; o.y += p * vv.y; o.z += p * vv.z; o.w += p * vv.w;
        }
        *(float4*)(out + (size_t)(rowbase + qi) * E_DIM + ec + e4) = o;
        __syncthreads();
    }
}

// ============================================================================
// launch (graph-capturable: two kernel launches, no sync, no alloc)
// inputs: x, Wq, bq, Wk, bk, Wv, bv, window_size(=64, fixed)
// ============================================================================
extern "C" void kernel_launch(void* const* d_in, const int* in_sizes, int n_in,
                              void* d_out, int out_size)
{
    const float* x  = (const float*)d_in[0];
    const float* Wq = (const float*)d_in[1];
    const float* bq = (const float*)d_in[2];
    const float* Wk = (const float*)d_in[3];
    const float* bk = (const float*)d_in[4];
    const float* Wv = (const float*)d_in[5];
    const float* bv = (const float*)d_in[6];
    (void)in_sizes; (void)n_in; (void)out_size;

    dim3 g1(M_ROWS / BM, 24);             // (32, 24) = 768 CTAs
    qkv_gemm<<<g1, 256>>>(x, Wq, Wk, Wv, bq, bk, bv);

    local_attn<<<B_BATCH * (L_SEQ / QB), 256>>>((float*)d_out);
}

// round 15
// speedup vs baseline: 1.3962x; 1.3962x over previous
#include <cuda_runtime.h>
#include <cuda_bf16.h>
#include <cstdint>

// Problem constants (fixed by setup_inputs): B=2, L=2048, E=512, window=64
#define L_SEQ   2048
#define E_DIM   512
#define B_BATCH 2
#define M_ROWS  (B_BATCH * L_SEQ)   // 4096

// ---------------- scratch (device globals; no allocation allowed) ----------
__device__ float g_q[M_ROWS * E_DIM];
__device__ float g_k[M_ROWS * E_DIM];
__device__ float g_v[M_ROWS * E_DIM];

// ---------------- tf32 mma helpers (proven in R12 GEMM) --------------------
__device__ __forceinline__ uint32_t cvt_tf32(float f) {
    uint32_t u;
    asm("cvt.rna.tf32.f32 %0, %1;" : "=r"(u) : "f"(f));
    return u;
}

__device__ __forceinline__ void mma_tf32(float c[4], const uint32_t a[4], const uint32_t b[2]) {
    asm volatile(
        "mma.sync.aligned.m16n8k8.row.col.f32.tf32.tf32.f32 "
        "{%0,%1,%2,%3}, {%4,%5,%6,%7}, {%8,%9}, {%0,%1,%2,%3};"
        : "+f"(c[0]), "+f"(c[1]), "+f"(c[2]), "+f"(c[3])
        : "r"(a[0]), "r"(a[1]), "r"(a[2]), "r"(a[3]), "r"(b[0]), "r"(b[1]));
}

// ============================================================================
// Kernel 1: QKV projection on tensor cores (UNCHANGED from R12: ~81us).
// ============================================================================
#define BM 128
#define BN 64
#define BK 16
#define KSTR (BK + 4)   // 20 -> conflict-free fragment loads

__global__ void __launch_bounds__(256, 2) qkv_gemm(
    const float* __restrict__ X,
    const float* __restrict__ Wq, const float* __restrict__ Wk, const float* __restrict__ Wv,
    const float* __restrict__ bq, const float* __restrict__ bk, const float* __restrict__ bv)
{
    __shared__ uint32_t As[2][BM][KSTR];   // 20480 B
    __shared__ uint32_t Bs[2][BN][KSTR];   // 10240 B

    const int t    = threadIdx.x;
    const int warp = t >> 5, lane = t & 31;
    const int wm   = warp & 3;
    const int wn   = warp >> 2;
    const int kq   = lane & 3;
    const int lr   = lane >> 2;

    const int m0  = blockIdx.x * BM;
    const int nb  = blockIdx.y;
    const int mat = nb >> 3;
    const int f0  = (nb & 7) * BN;

    const float* W    = (mat == 0) ? Wq : (mat == 1) ? Wk : Wv;
    const float* bias = (mat == 0) ? bq : (mat == 1) ? bk : bv;
    float*       out  = (mat == 0) ? g_q : (mat == 1) ? g_k : g_v;

    const int ra = t >> 1;
    const int ca = (t & 1) * 8;
    const int rb = t >> 2;
    const int cb = (t & 3) * 4;

    const float* Ag = X + (size_t)(m0 + ra) * E_DIM + ca;
    const float* Bg = W + (size_t)(f0 + rb) * E_DIM + cb;

    {
        float4 a0 = *(const float4*)(Ag);
        float4 a1 = *(const float4*)(Ag + 4);
        float4 b0 = *(const float4*)(Bg);
        uint4 ua0 = make_uint4(cvt_tf32(a0.x), cvt_tf32(a0.y), cvt_tf32(a0.z), cvt_tf32(a0.w));
        uint4 ua1 = make_uint4(cvt_tf32(a1.x), cvt_tf32(a1.y), cvt_tf32(a1.z), cvt_tf32(a1.w));
        uint4 ub0 = make_uint4(cvt_tf32(b0.x), cvt_tf32(b0.y), cvt_tf32(b0.z), cvt_tf32(b0.w));
        *(uint4*)&As[0][ra][ca]     = ua0;
        *(uint4*)&As[0][ra][ca + 4] = ua1;
        *(uint4*)&Bs[0][rb][cb]     = ub0;
    }
    __syncthreads();

    float acc[2][4][4];
#pragma unroll
    for (int mt = 0; mt < 2; mt++)
#pragma unroll
        for (int nt = 0; nt < 4; nt++)
#pragma unroll
            for (int i = 0; i < 4; i++) acc[mt][nt][i] = 0.f;

    int buf = 0;
    for (int kt = 0; kt < E_DIM; kt += BK) {
        float4 na0, na1, nb0;
        const bool more = (kt + BK) < E_DIM;
        if (more) {
            na0 = *(const float4*)(Ag + kt + BK);
            na1 = *(const float4*)(Ag + kt + BK + 4);
            nb0 = *(const float4*)(Bg + kt + BK);
        }

#pragma unroll
        for (int ks = 0; ks < BK; ks += 8) {
            uint32_t af[2][4], bf[4][2];
#pragma unroll
            for (int mt = 0; mt < 2; mt++) {
                int m = wm * 32 + mt * 16 + lr;
                af[mt][0] = As[buf][m][ks + kq];
                af[mt][1] = As[buf][m + 8][ks + kq];
                af[mt][2] = As[buf][m][ks + kq + 4];
                af[mt][3] = As[buf][m + 8][ks + kq + 4];
            }
#pragma unroll
            for (int nt = 0; nt < 4; nt++) {
                int n = wn * 32 + nt * 8 + lr;
                bf[nt][0] = Bs[buf][n][ks + kq];
                bf[nt][1] = Bs[buf][n][ks + kq + 4];
            }
#pragma unroll
            for (int mt = 0; mt < 2; mt++)
#pragma unroll
                for (int nt = 0; nt < 4; nt++)
                    mma_tf32(acc[mt][nt], af[mt], bf[nt]);
        }

        if (more) {
            int nbuf = buf ^ 1;
            uint4 ua0 = make_uint4(cvt_tf32(na0.x), cvt_tf32(na0.y), cvt_tf32(na0.z), cvt_tf32(na0.w));
            uint4 ua1 = make_uint4(cvt_tf32(na1.x), cvt_tf32(na1.y), cvt_tf32(na1.z), cvt_tf32(na1.w));
            uint4 ub0 = make_uint4(cvt_tf32(nb0.x), cvt_tf32(nb0.y), cvt_tf32(nb0.z), cvt_tf32(nb0.w));
            *(uint4*)&As[nbuf][ra][ca]     = ua0;
            *(uint4*)&As[nbuf][ra][ca + 4] = ua1;
            *(uint4*)&Bs[nbuf][rb][cb]     = ub0;
        }
        __syncthreads();
        buf ^= 1;
    }

#pragma unroll
    for (int mt = 0; mt < 2; mt++) {
#pragma unroll
        for (int nt = 0; nt < 4; nt++) {
            int row = m0 + wm * 32 + mt * 16 + lr;
            int col = f0 + wn * 32 + nt * 8 + 2 * kq;
            float2 bb = *(const float2*)(bias + col);
            *(float2*)(out + (size_t)row * E_DIM + col) =
                make_float2(acc[mt][nt][0] + bb.x, acc[mt][nt][1] + bb.y);
            *(float2*)(out + (size_t)(row + 8) * E_DIM + col) =
                make_float2(acc[mt][nt][2] + bb.x, acc[mt][nt][3] + bb.y);
        }
    }
}

// ============================================================================
// Kernel 2: sliding-window attention, TENSORIZED (tf32 m16n8k8).
// CTA = 16 queries, window = 144 keys [l0-64, l0+79]. 256 threads, 8 warps.
//
// FIX vs R14: P row stride padded 144 -> 160 (PSTR). The XOR swizzle
// col^((row&7)<<2) is only a bijection within complete 32-col blocks;
// with stride 144 the last (half) block swizzled up to index 159 -> smem
// OOB -> illegal memory access. With PSTR=160 all swizzled indices < 160
// and store/load mappings are consistent (only logical j<144 ever touched).
//
// Phase A: S[16 q][144 k] = Q.K^T, 16 e-chunks of 32 in smem (tf32).
// Softmax: 2 q-rows per warp; probs written back as tf32 bits.
// Phase B: O[16 q][512 e] = P.V, e-chunks of 64 (8 n8-tiles = 8 warps).
// All smem fragment loads conflict-free via XOR swizzles (verified per
// pattern). Register-staged prefetch overlaps LDG with MMA; V chunk 0
// prefetched before softmax. Static smem = 46 KB.
// ============================================================================
#define QB   16
#define KBW  144          // QB + 2*64
#define PSTR 160          // KBW padded to multiple of 32 (swizzle closure)

__global__ void __launch_bounds__(256) local_attn(float* __restrict__ out)
{
    __shared__ union {
        struct { uint32_t k[KBW][32]; uint32_t q[QB][32]; } a;  // 20480 B
        struct { uint32_t v[KBW][64]; } b;                      // 36864 B
    } S;
    __shared__ uint32_t P[QB][PSTR];                             // 10240 B

    const int t    = threadIdx.x;
    const int warp = t >> 5, lane = t & 31;
    const int lr   = lane >> 2, kq = lane & 3;
    const int sw   = lr << 2;             // swizzle for Q/K/P frag loads

    const int blk  = blockIdx.x;
    const int bb   = blk >> 7;            // batch
    const int l0   = (blk & 127) << 4;
    const int rowbase = bb * L_SEQ + l0;
    const int kbase   = l0 - 64;          // global index of local key 0

    float4 pf[9];                          // prefetch staging registers

    // ---- chunk loaders (phase A: 4xK float4 + 1 K-or-Q float4 per thread) --
    auto LDA = [&](int ec) {
#pragma unroll
        for (int i = 0; i < 4; i++) {
            int idx = t + (i << 8);
            int r = idx >> 3, c4 = (idx & 7) << 2;
            int g = kbase + r;
            pf[i] = (g >= 0 && g < L_SEQ)
                ? *(const float4*)(g_k + (size_t)(bb * L_SEQ + g) * E_DIM + ec + c4)
                : make_float4(0.f, 0.f, 0.f, 0.f);
        }
        if (t < 128) {
            int idx = 1024 + t;
            int r = idx >> 3, c4 = (idx & 7) << 2;
            int g = kbase + r;
            pf[4] = (g >= 0 && g < L_SEQ)
                ? *(const float4*)(g_k + (size_t)(bb * L_SEQ + g) * E_DIM + ec + c4)
                : make_float4(0.f, 0.f, 0.f, 0.f);
        } else {
            int idx = t - 128;
            int r = idx >> 3, c4 = (idx & 7) << 2;
            pf[4] = *(const float4*)(g_q + (size_t)(rowbase + r) * E_DIM + ec + c4);
        }
    };
    auto STA = [&]() {
#pragma unroll
        for (int i = 0; i < 4; i++) {
            int idx = t + (i << 8);
            int r = idx >> 3, c4 = (idx & 7) << 2;
            uint4 u = make_uint4(cvt_tf32(pf[i].x), cvt_tf32(pf[i].y),
                                 cvt_tf32(pf[i].z), cvt_tf32(pf[i].w));
            *(uint4*)&S.a.k[r][c4 ^ ((r & 7) << 2)] = u;
        }
        uint4 u = make_uint4(cvt_tf32(pf[4].x), cvt_tf32(pf[4].y),
                             cvt_tf32(pf[4].z), cvt_tf32(pf[4].w));
        if (t < 128) {
            int idx = 1024 + t;
            int r = idx >> 3, c4 = (idx & 7) << 2;
            *(uint4*)&S.a.k[r][c4 ^ ((r & 7) << 2)] = u;
        } else {
            int idx = t - 128;
            int r = idx >> 3, c4 = (idx & 7) << 2;
            *(uint4*)&S.a.q[r][c4 ^ ((r & 7) << 2)] = u;
        }
    };

    // ---------------- Phase A: scores on tensor cores ----------------
    float accA0[4] = {0,0,0,0}, accA1[4] = {0,0,0,0}, accA2[4] = {0,0,0,0};
    const bool has3 = (warp < 2);
    const int n0a = warp << 3, n1a = (warp + 8) << 3, n2a = (16 + warp) << 3;

    LDA(0);
    for (int c = 0; c < 16; c++) {
        __syncthreads();
        STA();
        __syncthreads();
        if (c < 15) LDA((c + 1) << 5);
#pragma unroll
        for (int ks = 0; ks < 32; ks += 8) {
            uint32_t af[4];
            af[0] = S.a.q[lr    ][(ks + kq    ) ^ sw];
            af[1] = S.a.q[lr + 8][(ks + kq    ) ^ sw];
            af[2] = S.a.q[lr    ][(ks + kq + 4) ^ sw];
            af[3] = S.a.q[lr + 8][(ks + kq + 4) ^ sw];
            uint32_t bf[2];
            bf[0] = S.a.k[n0a + lr][(ks + kq    ) ^ sw];
            bf[1] = S.a.k[n0a + lr][(ks + kq + 4) ^ sw];
            mma_tf32(accA0, af, bf);
            bf[0] = S.a.k[n1a + lr][(ks + kq    ) ^ sw];
            bf[1] = S.a.k[n1a + lr][(ks + kq + 4) ^ sw];
            mma_tf32(accA1, af, bf);
            if (has3) {
                bf[0] = S.a.k[n2a + lr][(ks + kq    ) ^ sw];
                bf[1] = S.a.k[n2a + lr][(ks + kq + 4) ^ sw];
                mma_tf32(accA2, af, bf);
            }
        }
    }

    // scale + mask -> P (q-major, swizzled, fp32 bits)
    const float scale = 0.044194173824159216f;   // 1/sqrt(512)
    auto PSTORE = [&](int q, int j, float v) {
        int g = kbase + j;
        bool valid = (g >= 0) && (g < L_SEQ) && (j >= q) && (j <= q + 128);
        P[q][j ^ ((q & 7) << 2)] = __float_as_uint(valid ? v * scale : -3.0e38f);
    };
    {
        int j0 = n0a + 2 * kq;
        PSTORE(lr,     j0,     accA0[0]); PSTORE(lr,     j0 + 1, accA0[1]);
        PSTORE(lr + 8, j0,     accA0[2]); PSTORE(lr + 8, j0 + 1, accA0[3]);
        j0 = n1a + 2 * kq;
        PSTORE(lr,     j0,     accA1[0]); PSTORE(lr,     j0 + 1, accA1[1]);
        PSTORE(lr + 8, j0,     accA1[2]); PSTORE(lr + 8, j0 + 1, accA1[3]);
        if (has3) {
            j0 = n2a + 2 * kq;
            PSTORE(lr,     j0,     accA2[0]); PSTORE(lr,     j0 + 1, accA2[1]);
            PSTORE(lr + 8, j0,     accA2[2]); PSTORE(lr + 8, j0 + 1, accA2[3]);
        }
    }

    // ---- prefetch V chunk 0 (overlaps with softmax) ----
    auto LDB = [&](int ec) {
#pragma unroll
        for (int i = 0; i < 9; i++) {
            int idx = t + (i << 8);
            int r = idx >> 4, c4 = (idx & 15) << 2;
            int g = kbase + r;
            pf[i] = (g >= 0 && g < L_SEQ)
                ? *(const float4*)(g_v + (size_t)(bb * L_SEQ + g) * E_DIM + ec + c4)
                : make_float4(0.f, 0.f, 0.f, 0.f);
        }
    };
    auto STB = [&]() {
#pragma unroll
        for (int i = 0; i < 9; i++) {
            int idx = t + (i << 8);
            int r = idx >> 4, c4 = (idx & 15) << 2;
            uint4 u = make_uint4(cvt_tf32(pf[i].x), cvt_tf32(pf[i].y),
                                 cvt_tf32(pf[i].z), cvt_tf32(pf[i].w));
            *(uint4*)&S.b.v[r][c4 ^ ((r & 3) << 3)] = u;
        }
    };
    LDB(0);
    __syncthreads();   // P complete across CTA

    // ---------------- softmax: 8 warps x 2 query-rows ----------------
#pragma unroll
    for (int qq = 0; qq < 2; qq++) {
        int r = (warp << 1) + qq;
        int rsw = (r & 7) << 2;
        float v[5];
#pragma unroll
        for (int i = 0; i < 5; i++) {
            int cc = lane + (i << 5);
            v[i] = (cc < KBW) ? __uint_as_float(P[r][cc ^ rsw]) : -3.0e38f;
        }
        float mx = fmaxf(fmaxf(fmaxf(v[0], v[1]), fmaxf(v[2], v[3])), v[4]);
#pragma unroll
        for (int o = 16; o; o >>= 1) mx = fmaxf(mx, __shfl_xor_sync(0xffffffffu, mx, o));
        float s = 0.f;
#pragma unroll
        for (int i = 0; i < 5; i++) { v[i] = __expf(v[i] - mx); s += v[i]; }
#pragma unroll
        for (int o = 16; o; o >>= 1) s += __shfl_xor_sync(0xffffffffu, s, o);
        float inv = 1.0f / s;
#pragma unroll
        for (int i = 0; i < 5; i++) {
            int cc = lane + (i << 5);
            if (cc < KBW) P[r][cc ^ rsw] = cvt_tf32(v[i] * inv);
        }
    }
    __syncthreads();

    // ---------------- Phase B: O = P . V on tensor cores ----------------
    const int ecol = warp << 3;            // this warp's 8 e-cols per chunk
    for (int c = 0; c < 8; c++) {
        STB();
        __syncthreads();
        if (c < 7) LDB((c + 1) << 6);
        float acc[4] = {0, 0, 0, 0};
#pragma unroll
        for (int k0 = 0; k0 < KBW; k0 += 8) {
            uint32_t af[4];
            af[0] = P[lr    ][(k0 + kq    ) ^ sw];
            af[1] = P[lr + 8][(k0 + kq    ) ^ sw];
            af[2] = P[lr    ][(k0 + kq + 4) ^ sw];
            af[3] = P[lr + 8][(k0 + kq + 4) ^ sw];
            uint32_t bf[2];
            bf[0] = S.b.v[k0 + kq    ][(ecol + lr) ^ (kq << 3)];
            bf[1] = S.b.v[k0 + kq + 4][(ecol + lr) ^ (kq << 3)];
            mma_tf32(acc, af, bf);
        }
        int col = (c << 6) + ecol + (kq << 1);
        *(float2*)(out + (size_t)(rowbase + lr) * E_DIM + col) =
            make_float2(acc[0], acc[1]);
        *(float2*)(out + (size_t)(rowbase + lr + 8) * E_DIM + col) =
            make_float2(acc[2], acc[3]);
        __syncthreads();
    }
}

// ============================================================================
// launch (graph-capturable: two kernel launches, no sync, no alloc)
// inputs: x, Wq, bq, Wk, bk, Wv, bv, window_size(=64, fixed)
// ============================================================================
extern "C" void kernel_launch(void* const* d_in, const int* in_sizes, int n_in,
                              void* d_out, int out_size)
{
    const float* x  = (const float*)d_in[0];
    const float* Wq = (const float*)d_in[1];
    const float* bq = (const float*)d_in[2];
    const float* Wk = (const float*)d_in[3];
    const float* bk = (const float*)d_in[4];
    const float* Wv = (const float*)d_in[5];
    const float* bv = (const float*)d_in[6];
    (void)in_sizes; (void)n_in; (void)out_size;

    dim3 g1(M_ROWS / BM, 24);             // (32, 24) = 768 CTAs
    qkv_gemm<<<g1, 256>>>(x, Wq, Wk, Wv, bq, bk, bv);

    local_attn<<<B_BATCH * (L_SEQ / QB), 256>>>((float*)d_out);
}

// round 17
// speedup vs baseline: 1.6985x; 1.2165x over previous
#include <cuda_runtime.h>
#include <cuda_bf16.h>
#include <cstdint>

// Problem constants (fixed by setup_inputs): B=2, L=2048, E=512, window=64
#define L_SEQ   2048
#define E_DIM   512
#define B_BATCH 2
#define M_ROWS  (B_BATCH * L_SEQ)   // 4096

// NOTE (R16 finding): this bench compiles for sm_103 (no 'a'), so tcgen05 /
// TMEM are NOT available. mma.sync tf32 (HMMA fallback) is the tensor path.

// ---------------- scratch (device globals; no allocation allowed) ----------
__device__ float g_q[M_ROWS * E_DIM];
__device__ float g_k[M_ROWS * E_DIM];
__device__ float g_v[M_ROWS * E_DIM];

// ---------------- tf32 mma helpers ----------------
__device__ __forceinline__ uint32_t cvt_tf32(float f) {
    uint32_t u;
    asm("cvt.rna.tf32.f32 %0, %1;" : "=r"(u) : "f"(f));
    return u;
}

__device__ __forceinline__ void mma_tf32(float c[4], const uint32_t a[4], const uint32_t b[2]) {
    asm volatile(
        "mma.sync.aligned.m16n8k8.row.col.f32.tf32.tf32.f32 "
        "{%0,%1,%2,%3}, {%4,%5,%6,%7}, {%8,%9}, {%0,%1,%2,%3};"
        : "+f"(c[0]), "+f"(c[1]), "+f"(c[2]), "+f"(c[3])
        : "r"(a[0]), "r"(a[1]), "r"(a[2]), "r"(a[3]), "r"(b[0]), "r"(b[1]));
}

// ============================================================================
// Kernel 1: FUSED QKV projection.  {q,k,v}[m][f] = sum_e X[m][e]W*[f][e] + b*
// One CTA computes the SAME 64x64 output tile for all three matrices, sharing
// the A (X) smem staging and its fragment loads:
//   - 3x MMA work per __syncthreads (24 vs 16 MMAs/warp/iter)
//   - LDS:MMA ratio 2.0 -> 1.67 (A-frags amortized over 3 acc sets)
//   - X LDG traffic /3 vs separate kernels
// Layout: stride-20 rows, bank = (20*lr + kq) % 32 bijective -> conflict-free
// (tile base offsets 64*20 and 3-matrix offsets 1280 u32 are = 0 mod 32).
// Double-buffered, register-staged prefetch, 1 sync per K-tile.
// grid = (M/64, 512/64) = (64, 8); 256 threads, warp grid 2m x 4n.
// ============================================================================
#define FM 64
#define FN 64
#define FK 16
#define FSTR (FK + 4)   // 20

__global__ void __launch_bounds__(256, 2) qkv_fused(
    const float* __restrict__ X,
    const float* __restrict__ Wq, const float* __restrict__ Wk, const float* __restrict__ Wv,
    const float* __restrict__ bq, const float* __restrict__ bk, const float* __restrict__ bv)
{
    __shared__ uint32_t As[2][FM][FSTR];        // 10240 B
    __shared__ uint32_t Bs[2][3][FN][FSTR];     // 30720 B

    const int t    = threadIdx.x;
    const int warp = t >> 5, lane = t & 31;
    const int wm   = warp & 1;              // 2 m-warps (32 rows)
    const int wn   = warp >> 1;             // 4 n-warps (16 cols)
    const int kq   = lane & 3;
    const int lr   = lane >> 2;

    const int m0 = blockIdx.x * FM;
    const int f0 = blockIdx.y * FN;

    // loader mapping: one float4 per thread per tile per operand
    const int r  = t >> 2;                  // 0..63
    const int c4 = (t & 3) << 2;            // 0,4,8,12
    const float* Ag  = X  + (size_t)(m0 + r) * E_DIM + c4;
    const float* Bg0 = Wq + (size_t)(f0 + r) * E_DIM + c4;
    const float* Bg1 = Wk + (size_t)(f0 + r) * E_DIM + c4;
    const float* Bg2 = Wv + (size_t)(f0 + r) * E_DIM + c4;

    // prologue: tile 0
    {
        float4 a  = *(const float4*)(Ag);
        float4 b0 = *(const float4*)(Bg0);
        float4 b1 = *(const float4*)(Bg1);
        float4 b2 = *(const float4*)(Bg2);
        *(uint4*)&As[0][r][c4]    = make_uint4(cvt_tf32(a.x),  cvt_tf32(a.y),  cvt_tf32(a.z),  cvt_tf32(a.w));
        *(uint4*)&Bs[0][0][r][c4] = make_uint4(cvt_tf32(b0.x), cvt_tf32(b0.y), cvt_tf32(b0.z), cvt_tf32(b0.w));
        *(uint4*)&Bs[0][1][r][c4] = make_uint4(cvt_tf32(b1.x), cvt_tf32(b1.y), cvt_tf32(b1.z), cvt_tf32(b1.w));
        *(uint4*)&Bs[0][2][r][c4] = make_uint4(cvt_tf32(b2.x), cvt_tf32(b2.y), cvt_tf32(b2.z), cvt_tf32(b2.w));
    }
    __syncthreads();

    float acc[3][2][2][4];
#pragma unroll
    for (int m = 0; m < 3; m++)
#pragma unroll
        for (int mt = 0; mt < 2; mt++)
#pragma unroll
            for (int nt = 0; nt < 2; nt++)
#pragma unroll
                for (int i = 0; i < 4; i++) acc[m][mt][nt][i] = 0.f;

    int buf = 0;
    for (int kt = 0; kt < E_DIM; kt += FK) {
        float4 na, nb0, nb1, nb2;
        const bool more = (kt + FK) < E_DIM;
        if (more) {
            na  = *(const float4*)(Ag  + kt + FK);
            nb0 = *(const float4*)(Bg0 + kt + FK);
            nb1 = *(const float4*)(Bg1 + kt + FK);
            nb2 = *(const float4*)(Bg2 + kt + FK);
        }

#pragma unroll
        for (int ks = 0; ks < FK; ks += 8) {
            uint32_t af[2][4];
#pragma unroll
            for (int mt = 0; mt < 2; mt++) {
                int mrow = wm * 32 + mt * 16 + lr;
                af[mt][0] = As[buf][mrow][ks + kq];
                af[mt][1] = As[buf][mrow + 8][ks + kq];
                af[mt][2] = As[buf][mrow][ks + kq + 4];
                af[mt][3] = As[buf][mrow + 8][ks + kq + 4];
            }
#pragma unroll
            for (int m = 0; m < 3; m++) {
                uint32_t bf[2][2];
#pragma unroll
                for (int nt = 0; nt < 2; nt++) {
                    int nrow = wn * 16 + nt * 8 + lr;
                    bf[nt][0] = Bs[buf][m][nrow][ks + kq];
                    bf[nt][1] = Bs[buf][m][nrow][ks + kq + 4];
                }
#pragma unroll
                for (int mt = 0; mt < 2; mt++)
#pragma unroll
                    for (int nt = 0; nt < 2; nt++)
                        mma_tf32(acc[m][mt][nt], af[mt], bf[nt]);
            }
        }

        if (more) {
            int nbuf = buf ^ 1;
            *(uint4*)&As[nbuf][r][c4]    = make_uint4(cvt_tf32(na.x),  cvt_tf32(na.y),  cvt_tf32(na.z),  cvt_tf32(na.w));
            *(uint4*)&Bs[nbuf][0][r][c4] = make_uint4(cvt_tf32(nb0.x), cvt_tf32(nb0.y), cvt_tf32(nb0.z), cvt_tf32(nb0.w));
            *(uint4*)&Bs[nbuf][1][r][c4] = make_uint4(cvt_tf32(nb1.x), cvt_tf32(nb1.y), cvt_tf32(nb1.z), cvt_tf32(nb1.w));
            *(uint4*)&Bs[nbuf][2][r][c4] = make_uint4(cvt_tf32(nb2.x), cvt_tf32(nb2.y), cvt_tf32(nb2.z), cvt_tf32(nb2.w));
        }
        __syncthreads();
        buf ^= 1;
    }

    // epilogue: bias + store, all three outputs
#pragma unroll
    for (int m = 0; m < 3; m++) {
        const float* bias = (m == 0) ? bq : (m == 1) ? bk : bv;
        float*       out  = (m == 0) ? g_q : (m == 1) ? g_k : g_v;
#pragma unroll
        for (int mt = 0; mt < 2; mt++) {
#pragma unroll
            for (int nt = 0; nt < 2; nt++) {
                int row = m0 + wm * 32 + mt * 16 + lr;
                int col = f0 + wn * 16 + nt * 8 + 2 * kq;
                float2 bb = *(const float2*)(bias + col);
                *(float2*)(out + (size_t)row * E_DIM + col) =
                    make_float2(acc[m][mt][nt][0] + bb.x, acc[m][mt][nt][1] + bb.y);
                *(float2*)(out + (size_t)(row + 8) * E_DIM + col) =
                    make_float2(acc[m][mt][nt][2] + bb.x, acc[m][mt][nt][3] + bb.y);
            }
        }
    }
}

// ============================================================================
// Kernel 2: sliding-window attention, tensorized tf32 (UNCHANGED from R15,
// 36.8us measured): padded-P swizzle, MMA phases A/B, prefetch-overlapped.
// ============================================================================
#define QB   16
#define KBW  144          // QB + 2*64
#define PSTR 160          // KBW padded to multiple of 32 (swizzle closure)

__global__ void __launch_bounds__(256) local_attn(float* __restrict__ out)
{
    __shared__ union {
        struct { uint32_t k[KBW][32]; uint32_t q[QB][32]; } a;  // 20480 B
        struct { uint32_t v[KBW][64]; } b;                      // 36864 B
    } S;
    __shared__ uint32_t P[QB][PSTR];                             // 10240 B

    const int t    = threadIdx.x;
    const int warp = t >> 5, lane = t & 31;
    const int lr   = lane >> 2, kq = lane & 3;
    const int sw   = lr << 2;

    const int blk  = blockIdx.x;
    const int bb   = blk >> 7;
    const int l0   = (blk & 127) << 4;
    const int rowbase = bb * L_SEQ + l0;
    const int kbase   = l0 - 64;

    float4 pf[9];

    auto LDA = [&](int ec) {
#pragma unroll
        for (int i = 0; i < 4; i++) {
            int idx = t + (i << 8);
            int r = idx >> 3, c4 = (idx & 7) << 2;
            int g = kbase + r;
            pf[i] = (g >= 0 && g < L_SEQ)
                ? *(const float4*)(g_k + (size_t)(bb * L_SEQ + g) * E_DIM + ec + c4)
                : make_float4(0.f, 0.f, 0.f, 0.f);
        }
        if (t < 128) {
            int idx = 1024 + t;
            int r = idx >> 3, c4 = (idx & 7) << 2;
            int g = kbase + r;
            pf[4] = (g >= 0 && g < L_SEQ)
                ? *(const float4*)(g_k + (size_t)(bb * L_SEQ + g) * E_DIM + ec + c4)
                : make_float4(0.f, 0.f, 0.f, 0.f);
        } else {
            int idx = t - 128;
            int r = idx >> 3, c4 = (idx & 7) << 2;
            pf[4] = *(const float4*)(g_q + (size_t)(rowbase + r) * E_DIM + ec + c4);
        }
    };
    auto STA = [&]() {
#pragma unroll
        for (int i = 0; i < 4; i++) {
            int idx = t + (i << 8);
            int r = idx >> 3, c4 = (idx & 7) << 2;
            uint4 u = make_uint4(cvt_tf32(pf[i].x), cvt_tf32(pf[i].y),
                                 cvt_tf32(pf[i].z), cvt_tf32(pf[i].w));
            *(uint4*)&S.a.k[r][c4 ^ ((r & 7) << 2)] = u;
        }
        uint4 u = make_uint4(cvt_tf32(pf[4].x), cvt_tf32(pf[4].y),
                             cvt_tf32(pf[4].z), cvt_tf32(pf[4].w));
        if (t < 128) {
            int idx = 1024 + t;
            int r = idx >> 3, c4 = (idx & 7) << 2;
            *(uint4*)&S.a.k[r][c4 ^ ((r & 7) << 2)] = u;
        } else {
            int idx = t - 128;
            int r = idx >> 3, c4 = (idx & 7) << 2;
            *(uint4*)&S.a.q[r][c4 ^ ((r & 7) << 2)] = u;
        }
    };

    float accA0[4] = {0,0,0,0}, accA1[4] = {0,0,0,0}, accA2[4] = {0,0,0,0};
    const bool has3 = (warp < 2);
    const int n0a = warp << 3, n1a = (warp + 8) << 3, n2a = (16 + warp) << 3;

    LDA(0);
    for (int c = 0; c < 16; c++) {
        __syncthreads();
        STA();
        __syncthreads();
        if (c < 15) LDA((c + 1) << 5);
#pragma unroll
        for (int ks = 0; ks < 32; ks += 8) {
            uint32_t af[4];
            af[0] = S.a.q[lr    ][(ks + kq    ) ^ sw];
            af[1] = S.a.q[lr + 8][(ks + kq    ) ^ sw];
            af[2] = S.a.q[lr    ][(ks + kq + 4) ^ sw];
            af[3] = S.a.q[lr + 8][(ks + kq + 4) ^ sw];
            uint32_t bf[2];
            bf[0] = S.a.k[n0a + lr][(ks + kq    ) ^ sw];
            bf[1] = S.a.k[n0a + lr][(ks + kq + 4) ^ sw];
            mma_tf32(accA0, af, bf);
            bf[0] = S.a.k[n1a + lr][(ks + kq    ) ^ sw];
            bf[1] = S.a.k[n1a + lr][(ks + kq + 4) ^ sw];
            mma_tf32(accA1, af, bf);
            if (has3) {
                bf[0] = S.a.k[n2a + lr][(ks + kq    ) ^ sw];
                bf[1] = S.a.k[n2a + lr][(ks + kq + 4) ^ sw];
                mma_tf32(accA2, af, bf);
            }
        }
    }

    const float scale = 0.044194173824159216f;   // 1/sqrt(512)
    auto PSTORE = [&](int q, int j, float v) {
        int g = kbase + j;
        bool valid = (g >= 0) && (g < L_SEQ) && (j >= q) && (j <= q + 128);
        P[q][j ^ ((q & 7) << 2)] = __float_as_uint(valid ? v * scale : -3.0e38f);
    };
    {
        int j0 = n0a + 2 * kq;
        PSTORE(lr,     j0,     accA0[0]); PSTORE(lr,     j0 + 1, accA0[1]);
        PSTORE(lr + 8, j0,     accA0[2]); PSTORE(lr + 8, j0 + 1, accA0[3]);
        j0 = n1a + 2 * kq;
        PSTORE(lr,     j0,     accA1[0]); PSTORE(lr,     j0 + 1, accA1[1]);
        PSTORE(lr + 8, j0,     accA1[2]); PSTORE(lr + 8, j0 + 1, accA1[3]);
        if (has3) {
            j0 = n2a + 2 * kq;
            PSTORE(lr,     j0,     accA2[0]); PSTORE(lr,     j0 + 1, accA2[1]);
            PSTORE(lr + 8, j0,     accA2[2]); PSTORE(lr + 8, j0 + 1, accA2[3]);
        }
    }

    auto LDB = [&](int ec) {
#pragma unroll
        for (int i = 0; i < 9; i++) {
            int idx = t + (i << 8);
            int r = idx >> 4, c4 = (idx & 15) << 2;
            int g = kbase + r;
            pf[i] = (g >= 0 && g < L_SEQ)
                ? *(const float4*)(g_v + (size_t)(bb * L_SEQ + g) * E_DIM + ec + c4)
                : make_float4(0.f, 0.f, 0.f, 0.f);
        }
    };
    auto STB = [&]() {
#pragma unroll
        for (int i = 0; i < 9; i++) {
            int idx = t + (i << 8);
            int r = idx >> 4, c4 = (idx & 15) << 2;
            uint4 u = make_uint4(cvt_tf32(pf[i].x), cvt_tf32(pf[i].y),
                                 cvt_tf32(pf[i].z), cvt_tf32(pf[i].w));
            *(uint4*)&S.b.v[r][c4 ^ ((r & 3) << 3)] = u;
        }
    };
    LDB(0);
    __syncthreads();

#pragma unroll
    for (int qq = 0; qq < 2; qq++) {
        int r = (warp << 1) + qq;
        int rsw = (r & 7) << 2;
        float v[5];
#pragma unroll
        for (int i = 0; i < 5; i++) {
            int cc = lane + (i << 5);
            v[i] = (cc < KBW) ? __uint_as_float(P[r][cc ^ rsw]) : -3.0e38f;
        }
        float mx = fmaxf(fmaxf(fmaxf(v[0], v[1]), fmaxf(v[2], v[3])), v[4]);
#pragma unroll
        for (int o = 16; o; o >>= 1) mx = fmaxf(mx, __shfl_xor_sync(0xffffffffu, mx, o));
        float s = 0.f;
#pragma unroll
        for (int i = 0; i < 5; i++) { v[i] = __expf(v[i] - mx); s += v[i]; }
#pragma unroll
        for (int o = 16; o; o >>= 1) s += __shfl_xor_sync(0xffffffffu, s, o);
        float inv = 1.0f / s;
#pragma unroll
        for (int i = 0; i < 5; i++) {
            int cc = lane + (i << 5);
            if (cc < KBW) P[r][cc ^ rsw] = cvt_tf32(v[i] * inv);
        }
    }
    __syncthreads();

    const int ecol = warp << 3;
    for (int c = 0; c < 8; c++) {
        STB();
        __syncthreads();
        if (c < 7) LDB((c + 1) << 6);
        float acc[4] = {0, 0, 0, 0};
#pragma unroll
        for (int k0 = 0; k0 < KBW; k0 += 8) {
            uint32_t af[4];
            af[0] = P[lr    ][(k0 + kq    ) ^ sw];
            af[1] = P[lr + 8][(k0 + kq    ) ^ sw];
            af[2] = P[lr    ][(k0 + kq + 4) ^ sw];
            af[3] = P[lr + 8][(k0 + kq + 4) ^ sw];
            uint32_t bf[2];
            bf[0] = S.b.v[k0 + kq    ][(ecol + lr) ^ (kq << 3)];
            bf[1] = S.b.v[k0 + kq + 4][(ecol + lr) ^ (kq << 3)];
            mma_tf32(acc, af, bf);
        }
        int col = (c << 6) + ecol + (kq << 1);
        *(float2*)(out + (size_t)(rowbase + lr) * E_DIM + col) =
            make_float2(acc[0], acc[1]);
        *(float2*)(out + (size_t)(rowbase + lr + 8) * E_DIM + col) =
            make_float2(acc[2], acc[3]);
        __syncthreads();
    }
}

// ============================================================================
// launch (graph-capturable: two kernel launches, no sync, no alloc)
// inputs: x, Wq, bq, Wk, bk, Wv, bv, window_size(=64, fixed)
// ============================================================================
extern "C" void kernel_launch(void* const* d_in, const int* in_sizes, int n_in,
                              void* d_out, int out_size)
{
    const float* x  = (const float*)d_in[0];
    const float* Wq = (const float*)d_in[1];
    const float* bq = (const float*)d_in[2];
    const float* Wk = (const float*)d_in[3];
    const float* bk = (const float*)d_in[4];
    const float* Wv = (const float*)d_in[5];
    const float* bv = (const float*)d_in[6];
    (void)in_sizes; (void)n_in; (void)out_size;

    dim3 g1(M_ROWS / FM, E_DIM / FN);     // (64, 8) = 512 CTAs
    qkv_fused<<<g1, 256>>>(x, Wq, Wk, Wv, bq, bk, bv);

    local_attn<<<B_BATCH * (L_SEQ / QB), 256>>>((float*)d_out);
}